// round 1
// baseline (speedup 1.0000x reference)
#include <cuda_runtime.h>
#include <math.h>

#define Bsz 256
#define Lsz 24
#define Rsz 49
#define Fsz 2048
#define Esz 256
#define Hsz 512
#define Asz 512
#define Vsz 10000
#define STEPS 23
#define XK 2304      // E + F
#define GK 2816      // XK + H
#define G4 2048      // 4*H

// ---------------- scratch (static device globals; no allocations) ----------------
__device__ float g_fproj[Bsz * Rsz * Asz];   // (B*R, A)
__device__ float g_mean [Bsz * Fsz];         // (B, F)
__device__ float g_h    [Bsz * Hsz];
__device__ float g_c    [Bsz * Hsz];
__device__ float g_hp   [Bsz * Asz];
__device__ float g_x    [Bsz * XK];          // [emb | ctx]
__device__ float g_gates[Bsz * G4];

__device__ __forceinline__ float4 ld4(const float* p) {
    return *reinterpret_cast<const float4*>(p);
}

// ---------------------------------------------------------------------------
// Generic NT GEMM: C[m,n] = act(sum_k A[m,k]*Bm[n,k] + bias[n])
// Requires M%64==0, N%64==0, K%16==0. A:(M,K) row-major, Bm:(N,K) row-major.
// ACT: 0 = none, 1 = tanh
// ---------------------------------------------------------------------------
template <int ACT>
__global__ __launch_bounds__(256) void gemm_nt(
    const float* __restrict__ A, const float* __restrict__ Bm,
    const float* __restrict__ bias, float* __restrict__ C,
    int M, int N, int K)
{
    const int m0 = blockIdx.y * 64;
    const int n0 = blockIdx.x * 64;
    const int tid = threadIdx.x;
    const int tx = tid & 15, ty = tid >> 4;
    const int lr = tid >> 2;          // 0..63
    const int lk = (tid & 3) * 4;     // 0,4,8,12

    __shared__ float As[16][65];
    __shared__ float Bs[16][65];

    float acc[4][4] = {};

    for (int k0 = 0; k0 < K; k0 += 16) {
        float4 av = ld4(&A [(m0 + lr) * K + k0 + lk]);
        float4 bv = ld4(&Bm[(n0 + lr) * K + k0 + lk]);
        __syncthreads();
        As[lk + 0][lr] = av.x; As[lk + 1][lr] = av.y;
        As[lk + 2][lr] = av.z; As[lk + 3][lr] = av.w;
        Bs[lk + 0][lr] = bv.x; Bs[lk + 1][lr] = bv.y;
        Bs[lk + 2][lr] = bv.z; Bs[lk + 3][lr] = bv.w;
        __syncthreads();
#pragma unroll
        for (int k = 0; k < 16; k++) {
            float a[4], b[4];
#pragma unroll
            for (int i = 0; i < 4; i++) a[i] = As[k][ty * 4 + i];
#pragma unroll
            for (int j = 0; j < 4; j++) b[j] = Bs[k][tx * 4 + j];
#pragma unroll
            for (int i = 0; i < 4; i++)
#pragma unroll
                for (int j = 0; j < 4; j++)
                    acc[i][j] = fmaf(a[i], b[j], acc[i][j]);
        }
    }

#pragma unroll
    for (int i = 0; i < 4; i++) {
        int m = m0 + ty * 4 + i;
#pragma unroll
        for (int j = 0; j < 4; j++) {
            int n = n0 + tx * 4 + j;
            float v = acc[i][j] + bias[n];
            if (ACT == 1) v = tanhf(v);
            C[m * N + n] = v;
        }
    }
}

// ---------------------------------------------------------------------------
// mean over R
// ---------------------------------------------------------------------------
__global__ void mean_kernel(const float* __restrict__ feats, float* __restrict__ mean)
{
    int b = blockIdx.x;
    for (int f = threadIdx.x; f < Fsz; f += blockDim.x) {
        float s = 0.f;
        for (int r = 0; r < Rsz; r++) s += feats[(b * Rsz + r) * Fsz + f];
        mean[b * Fsz + f] = s * (1.0f / Rsz);
    }
}

// ---------------------------------------------------------------------------
// Fused attention: scores -> softmax -> ctx, plus embedding gather, per batch row.
// One block per b, 256 threads.
// ---------------------------------------------------------------------------
__global__ __launch_bounds__(256) void attn_kernel(
    const float* __restrict__ feats, const float* __restrict__ Ws,
    const float* __restrict__ bs, const float* __restrict__ embW,
    const int* __restrict__ ids, const int* __restrict__ lengths, int t)
{
    int b = blockIdx.x;
    if (lengths[b] <= t) return;  // masked row: x stale but never consumed

    __shared__ float hp_s[Asz];
    __shared__ float ws_s[Asz];
    __shared__ float sc_s[64];

    int tid = threadIdx.x;
    hp_s[tid]       = g_hp[b * Asz + tid];
    hp_s[tid + 256] = g_hp[b * Asz + tid + 256];
    ws_s[tid]       = Ws[tid];
    ws_s[tid + 256] = Ws[tid + 256];
    __syncthreads();

    int warp = tid >> 5, lane = tid & 31;
    for (int r = warp; r < Rsz; r += 8) {
        const float* fp = &g_fproj[(b * Rsz + r) * Asz];
        float s = 0.f;
        for (int a = lane; a < Asz; a += 32)
            s += tanhf(fp[a] + hp_s[a]) * ws_s[a];
#pragma unroll
        for (int o = 16; o; o >>= 1) s += __shfl_down_sync(0xffffffffu, s, o);
        if (lane == 0) sc_s[r] = s + bs[0];
    }
    __syncthreads();

    if (warp == 0) {
        float v1 = (lane < Rsz) ? sc_s[lane] : -INFINITY;
        float v2 = (lane + 32 < Rsz) ? sc_s[lane + 32] : -INFINITY;
        float mx = fmaxf(v1, v2);
#pragma unroll
        for (int o = 16; o; o >>= 1) mx = fmaxf(mx, __shfl_xor_sync(0xffffffffu, mx, o));
        float e1 = (lane < Rsz) ? expf(v1 - mx) : 0.f;
        float e2 = (lane + 32 < Rsz) ? expf(v2 - mx) : 0.f;
        float sm = e1 + e2;
#pragma unroll
        for (int o = 16; o; o >>= 1) sm += __shfl_xor_sync(0xffffffffu, sm, o);
        float inv = 1.f / sm;
        if (lane < Rsz) sc_s[lane] = e1 * inv;
        if (lane + 32 < Rsz) sc_s[lane + 32] = e2 * inv;
    }
    __syncthreads();

    // ctx = alpha @ feats[b]   -> x[b, E:]
    for (int f = tid; f < Fsz; f += 256) {
        float acc = 0.f;
#pragma unroll 7
        for (int r = 0; r < Rsz; r++)
            acc = fmaf(sc_s[r], feats[(b * Rsz + r) * Fsz + f], acc);
        g_x[b * XK + Esz + f] = acc;
    }
    // embedding -> x[b, :E]   (E == blockDim)
    int id = ids[b * Lsz + t];
    g_x[b * XK + tid] = embW[id * Esz + tid];
}

// ---------------------------------------------------------------------------
// gates = [x|h] @ [W_ih|W_hh]^T + b_ih + b_hh  (M=256, N=2048, K=2816)
// Whole-tile early exit via sorted lengths.
// ---------------------------------------------------------------------------
__global__ __launch_bounds__(256) void gates_gemm(
    const float* __restrict__ W_ih, const float* __restrict__ W_hh,
    const float* __restrict__ b_ih, const float* __restrict__ b_hh,
    const int* __restrict__ lengths, int t)
{
    const int m0 = blockIdx.y * 64;
    if (lengths[m0] <= t) return;  // all rows in tile masked (sorted desc)
    const int n0 = blockIdx.x * 64;
    const int tid = threadIdx.x;
    const int tx = tid & 15, ty = tid >> 4;
    const int lr = tid >> 2;
    const int lk = (tid & 3) * 4;

    __shared__ float As[16][65];
    __shared__ float Bs[16][65];
    float acc[4][4] = {};

    for (int k0 = 0; k0 < GK; k0 += 16) {
        const float* Ap; const float* Bp; int kk, lda;
        if (k0 < XK) { Ap = g_x; Bp = W_ih; kk = k0;      lda = XK;  }
        else         { Ap = g_h; Bp = W_hh; kk = k0 - XK; lda = Hsz; }
        float4 av = ld4(&Ap[(m0 + lr) * lda + kk + lk]);
        float4 bv = ld4(&Bp[(n0 + lr) * lda + kk + lk]);
        __syncthreads();
        As[lk + 0][lr] = av.x; As[lk + 1][lr] = av.y;
        As[lk + 2][lr] = av.z; As[lk + 3][lr] = av.w;
        Bs[lk + 0][lr] = bv.x; Bs[lk + 1][lr] = bv.y;
        Bs[lk + 2][lr] = bv.z; Bs[lk + 3][lr] = bv.w;
        __syncthreads();
#pragma unroll
        for (int k = 0; k < 16; k++) {
            float a[4], b[4];
#pragma unroll
            for (int i = 0; i < 4; i++) a[i] = As[k][ty * 4 + i];
#pragma unroll
            for (int j = 0; j < 4; j++) b[j] = Bs[k][tx * 4 + j];
#pragma unroll
            for (int i = 0; i < 4; i++)
#pragma unroll
                for (int j = 0; j < 4; j++)
                    acc[i][j] = fmaf(a[i], b[j], acc[i][j]);
        }
    }

#pragma unroll
    for (int i = 0; i < 4; i++) {
        int m = m0 + ty * 4 + i;
#pragma unroll
        for (int j = 0; j < 4; j++) {
            int n = n0 + tx * 4 + j;
            g_gates[m * G4 + n] = acc[i][j] + b_ih[n] + b_hh[n];
        }
    }
}

// ---------------------------------------------------------------------------
// LSTM pointwise cell update (masked)
// ---------------------------------------------------------------------------
__global__ void lstm_pw(const int* __restrict__ lengths, int t)
{
    int idx = blockIdx.x * blockDim.x + threadIdx.x;  // B*H
    int b = idx >> 9;
    int j = idx & 511;
    if (lengths[b] <= t) return;
    const float* g = &g_gates[b * G4];
    float ig = 1.f / (1.f + expf(-g[j]));
    float fg = 1.f / (1.f + expf(-g[512 + j]));
    float gg = tanhf(g[1024 + j]);
    float og = 1.f / (1.f + expf(-g[1536 + j]));
    float cn = fg * g_c[idx] + ig * gg;
    g_c[idx] = cn;
    g_h[idx] = og * tanhf(cn);
}

// ---------------------------------------------------------------------------
// FC: out[b, t, :] = active ? h @ Wfc^T + bfc : 0    (M=256, N=10000, K=512)
// ---------------------------------------------------------------------------
__global__ __launch_bounds__(256) void fc_gemm(
    const float* __restrict__ Wfc, const float* __restrict__ bfc,
    const int* __restrict__ lengths, int t, float* __restrict__ out)
{
    const int m0 = blockIdx.y * 64;
    const int n0 = blockIdx.x * 64;
    const int tid = threadIdx.x;
    const int tx = tid & 15, ty = tid >> 4;

    if (lengths[m0] <= t) {
        // whole tile masked -> zeros
#pragma unroll
        for (int i = 0; i < 4; i++) {
            int m = m0 + ty * 4 + i;
            float* op = out + (m * STEPS + t) * Vsz;
#pragma unroll
            for (int j = 0; j < 4; j++) {
                int n = n0 + tx * 4 + j;
                if (n < Vsz) op[n] = 0.f;
            }
        }
        return;
    }

    const int lr = tid >> 2;
    const int lk = (tid & 3) * 4;
    __shared__ float As[16][65];
    __shared__ float Bs[16][65];
    float acc[4][4] = {};

    for (int k0 = 0; k0 < Hsz; k0 += 16) {
        float4 av = ld4(&g_h[(m0 + lr) * Hsz + k0 + lk]);
        int nr = n0 + lr;
        float4 bv = (nr < Vsz) ? ld4(&Wfc[nr * Hsz + k0 + lk])
                               : make_float4(0.f, 0.f, 0.f, 0.f);
        __syncthreads();
        As[lk + 0][lr] = av.x; As[lk + 1][lr] = av.y;
        As[lk + 2][lr] = av.z; As[lk + 3][lr] = av.w;
        Bs[lk + 0][lr] = bv.x; Bs[lk + 1][lr] = bv.y;
        Bs[lk + 2][lr] = bv.z; Bs[lk + 3][lr] = bv.w;
        __syncthreads();
#pragma unroll
        for (int k = 0; k < 16; k++) {
            float a[4], b[4];
#pragma unroll
            for (int i = 0; i < 4; i++) a[i] = As[k][ty * 4 + i];
#pragma unroll
            for (int j = 0; j < 4; j++) b[j] = Bs[k][tx * 4 + j];
#pragma unroll
            for (int i = 0; i < 4; i++)
#pragma unroll
                for (int j = 0; j < 4; j++)
                    acc[i][j] = fmaf(a[i], b[j], acc[i][j]);
        }
    }

#pragma unroll
    for (int i = 0; i < 4; i++) {
        int m = m0 + ty * 4 + i;
        bool active = (lengths[m] > t);
        float* op = out + (m * STEPS + t) * Vsz;
#pragma unroll
        for (int j = 0; j < 4; j++) {
            int n = n0 + tx * 4 + j;
            if (n < Vsz) op[n] = active ? (acc[i][j] + bfc[n]) : 0.f;
        }
    }
}

// ---------------------------------------------------------------------------
extern "C" void kernel_launch(void* const* d_in, const int* in_sizes, int n_in,
                              void* d_out, int out_size)
{
    const float* feats   = (const float*)d_in[0];
    const int*   ids     = (const int*)  d_in[1];
    const int*   lengths = (const int*)  d_in[2];
    const float* embW    = (const float*)d_in[3];
    const float* Wf      = (const float*)d_in[4];
    const float* bf      = (const float*)d_in[5];
    const float* Wh      = (const float*)d_in[6];
    const float* bh      = (const float*)d_in[7];
    const float* Ws      = (const float*)d_in[8];
    const float* bs      = (const float*)d_in[9];
    const float* W_ih    = (const float*)d_in[10];
    const float* b_ih    = (const float*)d_in[11];
    const float* W_hh    = (const float*)d_in[12];
    const float* b_hh    = (const float*)d_in[13];
    const float* Wfc     = (const float*)d_in[14];
    const float* bfc     = (const float*)d_in[15];
    const float* Wi_h    = (const float*)d_in[16];
    const float* bi_h    = (const float*)d_in[17];
    const float* Wi_c    = (const float*)d_in[18];
    const float* bi_c    = (const float*)d_in[19];
    float* out = (float*)d_out;

    void *p_mean, *p_h, *p_c, *p_hp, *p_fproj;
    cudaGetSymbolAddress(&p_mean,  g_mean);
    cudaGetSymbolAddress(&p_h,     g_h);
    cudaGetSymbolAddress(&p_c,     g_c);
    cudaGetSymbolAddress(&p_hp,    g_hp);
    cudaGetSymbolAddress(&p_fproj, g_fproj);
    float* mean  = (float*)p_mean;
    float* hbuf  = (float*)p_h;
    float* cbuf  = (float*)p_c;
    float* hpbuf = (float*)p_hp;
    float* fproj = (float*)p_fproj;

    // ---- precompute ----
    mean_kernel<<<Bsz, 256>>>(feats, mean);
    gemm_nt<1><<<dim3(Hsz / 64, Bsz / 64), 256>>>(mean, Wi_h, bi_h, hbuf, Bsz, Hsz, Fsz);
    gemm_nt<1><<<dim3(Hsz / 64, Bsz / 64), 256>>>(mean, Wi_c, bi_c, cbuf, Bsz, Hsz, Fsz);
    // f_proj = feats(12544,2048) @ Wf^T + bf
    gemm_nt<0><<<dim3(Asz / 64, (Bsz * Rsz) / 64), 256>>>(feats, Wf, bf, fproj,
                                                          Bsz * Rsz, Asz, Fsz);

    // ---- timesteps ----
    for (int t = 0; t < STEPS; t++) {
        // hp = h @ Wh^T + bh
        gemm_nt<0><<<dim3(Asz / 64, Bsz / 64), 256>>>(hbuf, Wh, bh, hpbuf, Bsz, Asz, Hsz);
        attn_kernel<<<Bsz, 256>>>(feats, Ws, bs, embW, ids, lengths, t);
        gates_gemm<<<dim3(G4 / 64, Bsz / 64), 256>>>(W_ih, W_hh, b_ih, b_hh, lengths, t);
        lstm_pw<<<(Bsz * Hsz) / 256, 256>>>(lengths, t);
        fc_gemm<<<dim3((Vsz + 63) / 64, Bsz / 64), 256>>>(Wfc, bfc, lengths, t, out);
    }
}

// round 2
// speedup vs baseline: 2.0081x; 2.0081x over previous
#include <cuda_runtime.h>
#include <cuda_bf16.h>
#include <math.h>

#define Bsz 256
#define Lsz 24
#define Rsz 49
#define Fsz 2048
#define Esz 256
#define Hsz 512
#define Asz 512
#define Vsz 10000
#define STEPS 23
#define XK 2304        // E + F
#define GK 2816        // XK + H
#define G4 2048        // 4*H
#define VPAD 10112     // V padded to multiple of 128
#define NFEAT (Bsz * Rsz * Fsz)

typedef __nv_bfloat16 bf16;

// ---------------- scratch (static device globals) ----------------
__device__ float g_fproj[Bsz * Rsz * Asz];
__device__ bf16  g_featH[NFEAT], g_featL[NFEAT];
__device__ bf16  g_meanH[Bsz * Fsz], g_meanL[Bsz * Fsz];
__device__ bf16  g_WfH[Asz * Fsz],  g_WfL[Asz * Fsz];
__device__ bf16  g_WhH[Asz * Hsz],  g_WhL[Asz * Hsz];
__device__ bf16  g_WgH[G4 * GK],    g_WgL[G4 * GK];
__device__ bf16  g_WiH[1024 * Fsz], g_WiL[1024 * Fsz];
__device__ float g_bi[1024];
__device__ bf16  g_WfcH[VPAD * Hsz], g_WfcL[VPAD * Hsz];
__device__ float g_h0c0[Bsz * 1024];
__device__ float g_c[Bsz * Hsz];
__device__ bf16  g_hH[Bsz * Hsz], g_hL[Bsz * Hsz];
__device__ bf16  g_xhH[Bsz * GK], g_xhL[Bsz * GK];
__device__ float g_hp[Bsz * Asz];
__device__ float g_gpart[4 * Bsz * G4];

__device__ __forceinline__ void split2(float x, bf16& h, bf16& l) {
    h = __float2bfloat16(x);
    l = __float2bfloat16(x - __bfloat162float(h));
}

__device__ __forceinline__ void mma_bf16(float* c, const unsigned* a, const unsigned* b) {
    asm volatile(
        "mma.sync.aligned.m16n8k16.row.col.f32.bf16.bf16.f32 "
        "{%0,%1,%2,%3},{%4,%5,%6,%7},{%8,%9},{%0,%1,%2,%3};\n"
        : "+f"(c[0]), "+f"(c[1]), "+f"(c[2]), "+f"(c[3])
        : "r"(a[0]), "r"(a[1]), "r"(a[2]), "r"(a[3]), "r"(b[0]), "r"(b[1]));
}

// ---------------------------------------------------------------------------
// Tensor-core GEMM: C(M,N) = epi( A(M,K) @ B(N,K)^T )
// A,B in split bf16 (hi/lo). Block tile 128x128, BK=32, 8 warps (2x4),
// warp tile 64x32. 3-term split emulation: AhBh + AlBh + AhBl.
// EPI: 0 = +bias store        (fproj / hp)
//      1 = split-K partial, early exit by lengths (gates)
//      2 = fc: ragged mask, bias, zero fast path, n<Vsz guard
//      3 = tanh(+bias)        (h0c0)
// ---------------------------------------------------------------------------
template <int EPI>
__global__ __launch_bounds__(256) void mma_gemm(
    const bf16* __restrict__ Ah, const bf16* __restrict__ Al,
    const bf16* __restrict__ Bh, const bf16* __restrict__ Bl,
    const float* __restrict__ bias, float* __restrict__ C,
    int M, int N, int K, int kspl,
    const int* __restrict__ lengths, int t)
{
    const int m0 = blockIdx.y * 128;
    const int n0 = blockIdx.x * 128;
    const int tid = threadIdx.x;

    if (EPI == 1 || EPI == 2) {
        if (lengths[m0] <= t) {
            if (EPI == 2) {
                // whole tile masked: write zeros
                for (int i = tid; i < 128 * 128; i += 256) {
                    int r = i >> 7, cc = i & 127;
                    int n = n0 + cc;
                    if (n < Vsz)
                        C[((size_t)(m0 + r) * STEPS + t) * Vsz + n] = 0.f;
                }
            }
            return;
        }
    }

    __shared__ __align__(16) bf16 sAh[128 * 40];
    __shared__ __align__(16) bf16 sAl[128 * 40];
    __shared__ __align__(16) bf16 sBh[128 * 40];
    __shared__ __align__(16) bf16 sBl[128 * 40];

    const int lane = tid & 31, warp = tid >> 5;
    const int wm = warp >> 2, wn = warp & 3;   // 2 x 4
    const int grp = lane >> 2, tig = lane & 3;

    float acc[4][4][4] = {};

    const int kbase = (EPI == 1) ? blockIdx.z * kspl : 0;
    const int kcnt = kspl;

    uint4* s4Ah = (uint4*)sAh; uint4* s4Al = (uint4*)sAl;
    uint4* s4Bh = (uint4*)sBh; uint4* s4Bl = (uint4*)sBl;
    const unsigned* uAh = (const unsigned*)sAh;
    const unsigned* uAl = (const unsigned*)sAl;
    const unsigned* uBh = (const unsigned*)sBh;
    const unsigned* uBl = (const unsigned*)sBl;

    for (int kc = 0; kc < kcnt; kc += 32) {
        const int kg = kbase + kc;
#pragma unroll
        for (int i = 0; i < 2; i++) {
            int idx = tid + i * 256;
            int r = idx >> 2, cq = idx & 3;
            size_t ga = (size_t)(m0 + r) * K + kg + cq * 8;
            size_t gb = (size_t)(n0 + r) * K + kg + cq * 8;
            uint4 vah = *(const uint4*)(Ah + ga);
            uint4 val = *(const uint4*)(Al + ga);
            uint4 vbh = *(const uint4*)(Bh + gb);
            uint4 vbl = *(const uint4*)(Bl + gb);
            __syncthreads();   // only needed once per iter; placed before first store
            s4Ah[r * 5 + cq] = vah;
            s4Al[r * 5 + cq] = val;
            s4Bh[r * 5 + cq] = vbh;
            s4Bl[r * 5 + cq] = vbl;
        }
        __syncthreads();

#pragma unroll
        for (int k16 = 0; k16 < 2; k16++) {
            const int kq = k16 * 8 + tig;
            unsigned ah[4][4], al[4][4];
#pragma unroll
            for (int mt = 0; mt < 4; mt++) {
                int r0 = wm * 64 + mt * 16 + grp;
                ah[mt][0] = uAh[r0 * 20 + kq];
                ah[mt][1] = uAh[(r0 + 8) * 20 + kq];
                ah[mt][2] = uAh[r0 * 20 + kq + 4];
                ah[mt][3] = uAh[(r0 + 8) * 20 + kq + 4];
                al[mt][0] = uAl[r0 * 20 + kq];
                al[mt][1] = uAl[(r0 + 8) * 20 + kq];
                al[mt][2] = uAl[r0 * 20 + kq + 4];
                al[mt][3] = uAl[(r0 + 8) * 20 + kq + 4];
            }
#pragma unroll
            for (int nt = 0; nt < 4; nt++) {
                int nr = wn * 32 + nt * 8 + grp;
                unsigned bh[2] = { uBh[nr * 20 + kq], uBh[nr * 20 + kq + 4] };
                unsigned bl[2] = { uBl[nr * 20 + kq], uBl[nr * 20 + kq + 4] };
#pragma unroll
                for (int mt = 0; mt < 4; mt++) {
                    mma_bf16(acc[mt][nt], ah[mt], bh);
                    mma_bf16(acc[mt][nt], al[mt], bh);
                    mma_bf16(acc[mt][nt], ah[mt], bl);
                }
            }
        }
    }

    // -------- epilogue --------
    float* Cp = C;
    if (EPI == 1) Cp = C + (size_t)blockIdx.z * M * N;

#pragma unroll
    for (int mt = 0; mt < 4; mt++) {
#pragma unroll
        for (int nt = 0; nt < 4; nt++) {
            int row = m0 + wm * 64 + mt * 16 + grp;
            int col = n0 + wn * 32 + nt * 8 + tig * 2;
            float* a = acc[mt][nt];
            if (EPI == 0) {
                Cp[(size_t)row * N + col]           = a[0] + bias[col];
                Cp[(size_t)row * N + col + 1]       = a[1] + bias[col + 1];
                Cp[(size_t)(row + 8) * N + col]     = a[2] + bias[col];
                Cp[(size_t)(row + 8) * N + col + 1] = a[3] + bias[col + 1];
            } else if (EPI == 3) {
                Cp[(size_t)row * N + col]           = tanhf(a[0] + bias[col]);
                Cp[(size_t)row * N + col + 1]       = tanhf(a[1] + bias[col + 1]);
                Cp[(size_t)(row + 8) * N + col]     = tanhf(a[2] + bias[col]);
                Cp[(size_t)(row + 8) * N + col + 1] = tanhf(a[3] + bias[col + 1]);
            } else if (EPI == 1) {
                Cp[(size_t)row * N + col]           = a[0];
                Cp[(size_t)row * N + col + 1]       = a[1];
                Cp[(size_t)(row + 8) * N + col]     = a[2];
                Cp[(size_t)(row + 8) * N + col + 1] = a[3];
            } else { // EPI == 2 : fc
                if (col < Vsz) {
                    bool act0 = lengths[row] > t;
                    bool act1 = lengths[row + 8] > t;
                    float* p0 = C + ((size_t)row * STEPS + t) * Vsz;
                    float* p1 = C + ((size_t)(row + 8) * STEPS + t) * Vsz;
                    p0[col]     = act0 ? (a[0] + bias[col])     : 0.f;
                    p0[col + 1] = act0 ? (a[1] + bias[col + 1]) : 0.f;
                    p1[col]     = act1 ? (a[2] + bias[col])     : 0.f;
                    p1[col + 1] = act1 ? (a[3] + bias[col + 1]) : 0.f;
                }
            }
        }
    }
}

// ---------------------------------------------------------------------------
// conversion / setup kernels
// ---------------------------------------------------------------------------
__global__ void split_arr(const float* __restrict__ src, bf16* __restrict__ h,
                          bf16* __restrict__ l, int n)
{
    for (int i = blockIdx.x * blockDim.x + threadIdx.x; i < n; i += gridDim.x * blockDim.x)
        split2(src[i], h[i], l[i]);
}

__global__ void build_Wg(const float* __restrict__ Wih, const float* __restrict__ Whh,
                         bf16* __restrict__ h, bf16* __restrict__ l)
{
    for (int i = blockIdx.x * blockDim.x + threadIdx.x; i < G4 * GK; i += gridDim.x * blockDim.x) {
        int r = i / GK, cc = i % GK;
        float v = (cc < XK) ? Wih[(size_t)r * XK + cc] : Whh[(size_t)r * Hsz + cc - XK];
        split2(v, h[i], l[i]);
    }
}

__global__ void build_Wi(const float* __restrict__ Wih, const float* __restrict__ Wic,
                         const float* __restrict__ bih, const float* __restrict__ bic,
                         bf16* __restrict__ h, bf16* __restrict__ l, float* __restrict__ bi)
{
    for (int i = blockIdx.x * blockDim.x + threadIdx.x; i < 1024 * Fsz; i += gridDim.x * blockDim.x) {
        int r = i / Fsz, cc = i % Fsz;
        float v = (r < Hsz) ? Wih[(size_t)r * Fsz + cc] : Wic[(size_t)(r - Hsz) * Fsz + cc];
        split2(v, h[i], l[i]);
        if (i < 1024) bi[i] = (i < Hsz) ? bih[i] : bic[i - Hsz];
    }
}

__global__ void build_Wfc(const float* __restrict__ W, bf16* __restrict__ h, bf16* __restrict__ l)
{
    for (int i = blockIdx.x * blockDim.x + threadIdx.x; i < VPAD * Hsz; i += gridDim.x * blockDim.x) {
        int r = i / Hsz;
        float v = (r < Vsz) ? W[i] : 0.f;
        split2(v, h[i], l[i]);
    }
}

__global__ void mean_split(const float* __restrict__ feats, bf16* __restrict__ mh, bf16* __restrict__ ml)
{
    int b = blockIdx.x;
    for (int f = threadIdx.x; f < Fsz; f += blockDim.x) {
        float s = 0.f;
        for (int r = 0; r < Rsz; r++) s += feats[(size_t)(b * Rsz + r) * Fsz + f];
        split2(s * (1.0f / Rsz), mh[b * Fsz + f], ml[b * Fsz + f]);
    }
}

__global__ void init_state()
{
    int idx = blockIdx.x * blockDim.x + threadIdx.x;   // B*H
    int b = idx >> 9, j = idx & 511;
    float h = g_h0c0[b * 1024 + j];
    float c = g_h0c0[b * 1024 + 512 + j];
    g_c[idx] = c;
    split2(h, g_hH[idx], g_hL[idx]);
    split2(h, g_xhH[b * GK + XK + j], g_xhL[b * GK + XK + j]);
}

// ---------------------------------------------------------------------------
// Fused attention: scores -> softmax -> ctx + embedding gather; writes xh hi/lo
// ---------------------------------------------------------------------------
__global__ __launch_bounds__(256) void attn_kernel(
    const float* __restrict__ feats, const float* __restrict__ Ws,
    const float* __restrict__ bs, const float* __restrict__ embW,
    const int* __restrict__ ids, const int* __restrict__ lengths, int t)
{
    int b = blockIdx.x;
    if (lengths[b] <= t) return;

    __shared__ float hp_s[Asz];
    __shared__ float ws_s[Asz];
    __shared__ float sc_s[64];

    int tid = threadIdx.x;
    hp_s[tid]       = g_hp[b * Asz + tid];
    hp_s[tid + 256] = g_hp[b * Asz + tid + 256];
    ws_s[tid]       = Ws[tid];
    ws_s[tid + 256] = Ws[tid + 256];
    __syncthreads();

    int warp = tid >> 5, lane = tid & 31;
    for (int r = warp; r < Rsz; r += 8) {
        const float* fp = &g_fproj[(size_t)(b * Rsz + r) * Asz];
        float s = 0.f;
        for (int a = lane; a < Asz; a += 32)
            s += tanhf(fp[a] + hp_s[a]) * ws_s[a];
#pragma unroll
        for (int o = 16; o; o >>= 1) s += __shfl_down_sync(0xffffffffu, s, o);
        if (lane == 0) sc_s[r] = s + bs[0];
    }
    __syncthreads();

    if (warp == 0) {
        float v1 = (lane < Rsz) ? sc_s[lane] : -INFINITY;
        float v2 = (lane + 32 < Rsz) ? sc_s[lane + 32] : -INFINITY;
        float mx = fmaxf(v1, v2);
#pragma unroll
        for (int o = 16; o; o >>= 1) mx = fmaxf(mx, __shfl_xor_sync(0xffffffffu, mx, o));
        float e1 = (lane < Rsz) ? expf(v1 - mx) : 0.f;
        float e2 = (lane + 32 < Rsz) ? expf(v2 - mx) : 0.f;
        float sm = e1 + e2;
#pragma unroll
        for (int o = 16; o; o >>= 1) sm += __shfl_xor_sync(0xffffffffu, sm, o);
        float inv = 1.f / sm;
        if (lane < Rsz) sc_s[lane] = e1 * inv;
        if (lane + 32 < Rsz) sc_s[lane + 32] = e2 * inv;
    }
    __syncthreads();

    // ctx -> xh cols [E, E+F)
    for (int f = tid; f < Fsz; f += 256) {
        float acc = 0.f;
#pragma unroll 7
        for (int r = 0; r < Rsz; r++)
            acc = fmaf(sc_s[r], feats[(size_t)(b * Rsz + r) * Fsz + f], acc);
        split2(acc, g_xhH[b * GK + Esz + f], g_xhL[b * GK + Esz + f]);
    }
    // embedding -> xh cols [0, E)
    int id = ids[b * Lsz + t];
    split2(embW[(size_t)id * Esz + tid], g_xhH[b * GK + tid], g_xhL[b * GK + tid]);
}

// ---------------------------------------------------------------------------
// LSTM pointwise: sum 4 split-K parts + biases, update c/h (+ hi/lo copies)
// ---------------------------------------------------------------------------
__global__ void lstm_pw(const float* __restrict__ bih, const float* __restrict__ bhh,
                        const int* __restrict__ lengths, int t)
{
    int idx = blockIdx.x * blockDim.x + threadIdx.x;   // B*H
    int b = idx >> 9, j = idx & 511;
    if (lengths[b] <= t) return;
    const int MN = Bsz * G4;
    int base = b * G4;

    float gi = g_gpart[base + j]          + g_gpart[MN + base + j]
             + g_gpart[2 * MN + base + j] + g_gpart[3 * MN + base + j]
             + bih[j] + bhh[j];
    float gf = g_gpart[base + 512 + j]          + g_gpart[MN + base + 512 + j]
             + g_gpart[2 * MN + base + 512 + j] + g_gpart[3 * MN + base + 512 + j]
             + bih[512 + j] + bhh[512 + j];
    float gg = g_gpart[base + 1024 + j]          + g_gpart[MN + base + 1024 + j]
             + g_gpart[2 * MN + base + 1024 + j] + g_gpart[3 * MN + base + 1024 + j]
             + bih[1024 + j] + bhh[1024 + j];
    float go = g_gpart[base + 1536 + j]          + g_gpart[MN + base + 1536 + j]
             + g_gpart[2 * MN + base + 1536 + j] + g_gpart[3 * MN + base + 1536 + j]
             + bih[1536 + j] + bhh[1536 + j];

    float ig = 1.f / (1.f + expf(-gi));
    float fg = 1.f / (1.f + expf(-gf));
    float g  = tanhf(gg);
    float og = 1.f / (1.f + expf(-go));
    float cn = fg * g_c[idx] + ig * g;
    float hn = og * tanhf(cn);
    g_c[idx] = cn;
    split2(hn, g_hH[idx], g_hL[idx]);
    split2(hn, g_xhH[b * GK + XK + j], g_xhL[b * GK + XK + j]);
}

// ---------------------------------------------------------------------------
extern "C" void kernel_launch(void* const* d_in, const int* in_sizes, int n_in,
                              void* d_out, int out_size)
{
    const float* feats   = (const float*)d_in[0];
    const int*   ids     = (const int*)  d_in[1];
    const int*   lengths = (const int*)  d_in[2];
    const float* embW    = (const float*)d_in[3];
    const float* Wf      = (const float*)d_in[4];
    const float* bf      = (const float*)d_in[5];
    const float* Wh      = (const float*)d_in[6];
    const float* bh      = (const float*)d_in[7];
    const float* Ws      = (const float*)d_in[8];
    const float* bs      = (const float*)d_in[9];
    const float* W_ih    = (const float*)d_in[10];
    const float* b_ih    = (const float*)d_in[11];
    const float* W_hh    = (const float*)d_in[12];
    const float* b_hh    = (const float*)d_in[13];
    const float* Wfc     = (const float*)d_in[14];
    const float* bfc     = (const float*)d_in[15];
    const float* Wi_h    = (const float*)d_in[16];
    const float* bi_h    = (const float*)d_in[17];
    const float* Wi_c    = (const float*)d_in[18];
    const float* bi_c    = (const float*)d_in[19];
    float* out = (float*)d_out;

    // resolve device globals
    void *pv;
    cudaGetSymbolAddress(&pv, g_featH);  bf16* featH = (bf16*)pv;
    cudaGetSymbolAddress(&pv, g_featL);  bf16* featL = (bf16*)pv;
    cudaGetSymbolAddress(&pv, g_meanH);  bf16* meanH = (bf16*)pv;
    cudaGetSymbolAddress(&pv, g_meanL);  bf16* meanL = (bf16*)pv;
    cudaGetSymbolAddress(&pv, g_WfH);    bf16* WfH = (bf16*)pv;
    cudaGetSymbolAddress(&pv, g_WfL);    bf16* WfL = (bf16*)pv;
    cudaGetSymbolAddress(&pv, g_WhH);    bf16* WhH = (bf16*)pv;
    cudaGetSymbolAddress(&pv, g_WhL);    bf16* WhL = (bf16*)pv;
    cudaGetSymbolAddress(&pv, g_WgH);    bf16* WgH = (bf16*)pv;
    cudaGetSymbolAddress(&pv, g_WgL);    bf16* WgL = (bf16*)pv;
    cudaGetSymbolAddress(&pv, g_WiH);    bf16* WiH = (bf16*)pv;
    cudaGetSymbolAddress(&pv, g_WiL);    bf16* WiL = (bf16*)pv;
    cudaGetSymbolAddress(&pv, g_bi);     float* bi = (float*)pv;
    cudaGetSymbolAddress(&pv, g_WfcH);   bf16* WfcH = (bf16*)pv;
    cudaGetSymbolAddress(&pv, g_WfcL);   bf16* WfcL = (bf16*)pv;
    cudaGetSymbolAddress(&pv, g_h0c0);   float* h0c0 = (float*)pv;
    cudaGetSymbolAddress(&pv, g_hH);     bf16* hH = (bf16*)pv;
    cudaGetSymbolAddress(&pv, g_hL);     bf16* hL = (bf16*)pv;
    cudaGetSymbolAddress(&pv, g_xhH);    bf16* xhH = (bf16*)pv;
    cudaGetSymbolAddress(&pv, g_xhL);    bf16* xhL = (bf16*)pv;
    cudaGetSymbolAddress(&pv, g_hp);     float* hp = (float*)pv;
    cudaGetSymbolAddress(&pv, g_fproj);  float* fproj = (float*)pv;
    cudaGetSymbolAddress(&pv, g_gpart);  float* gpart = (float*)pv;

    // ---- weight / input conversion (cheap, every call) ----
    split_arr<<<1024, 256>>>(feats, featH, featL, NFEAT);
    split_arr<<<256, 256>>>(Wf, WfH, WfL, Asz * Fsz);
    split_arr<<<128, 256>>>(Wh, WhH, WhL, Asz * Hsz);
    build_Wg<<<512, 256>>>(W_ih, W_hh, WgH, WgL);
    build_Wi<<<256, 256>>>(Wi_h, Wi_c, bi_h, bi_c, WiH, WiL, bi);
    build_Wfc<<<512, 256>>>(Wfc, WfcH, WfcL);
    mean_split<<<Bsz, 256>>>(feats, meanH, meanL);

    // ---- init state: [h0|c0] = tanh(mean @ [Wi_h;Wi_c]^T + bi) ----
    mma_gemm<3><<<dim3(8, 2, 1), 256>>>(meanH, meanL, WiH, WiL, bi, h0c0,
                                        Bsz, 1024, Fsz, Fsz, nullptr, 0);
    init_state<<<(Bsz * Hsz) / 256, 256>>>();

    // ---- f_proj = feats @ Wf^T + bf ----
    mma_gemm<0><<<dim3(4, 98, 1), 256>>>(featH, featL, WfH, WfL, bf, fproj,
                                         Bsz * Rsz, Asz, Fsz, Fsz, nullptr, 0);

    // ---- timesteps ----
    for (int t = 0; t < STEPS; t++) {
        // hp = h @ Wh^T + bh
        mma_gemm<0><<<dim3(4, 2, 1), 256>>>(hH, hL, WhH, WhL, bh, hp,
                                            Bsz, Asz, Hsz, Hsz, nullptr, 0);
        attn_kernel<<<Bsz, 256>>>(feats, Ws, bs, embW, ids, lengths, t);
        // gates (split-K x4): parts of [x|h] @ [W_ih|W_hh]^T
        mma_gemm<1><<<dim3(16, 2, 4), 256>>>(xhH, xhL, WgH, WgL, nullptr, gpart,
                                             Bsz, G4, GK, GK / 4, lengths, t);
        lstm_pw<<<(Bsz * Hsz) / 256, 256>>>(b_ih, b_hh, lengths, t);
        // fc: out = h @ Wfc^T + bfc (ragged)
        mma_gemm<2><<<dim3(VPAD / 128, 2, 1), 256>>>(hH, hL, WfcH, WfcL, bfc, out,
                                                     Bsz, VPAD, Hsz, Hsz, lengths, t);
    }
}